// round 1
// baseline (speedup 1.0000x reference)
#include <cuda_runtime.h>
#include <cuda_bf16.h>
#include <cstdint>

// ---------------------------------------------------------------------------
// BipartiteGConv: fused graph conv.
//   rhs = input@Wi + bi                [N_IN,64]
//   lhs = other@Wo                     [N_OT,64]
//   acc[i] = sum_{e: rj[e]=i} lrelu(rhs[rj]+lhs[lj]+w_e*We)   (edge kernel, red.v4)
//   cnt[i] = #edges with rj[e]=i
//   out = acc@(Wf@WoutA) + cnt*(bf@WoutA) + input@WoutB + bout   (fused epilogue)
// where WoutA = Wout[0:64,:], WoutB = Wout[64:128,:]
// ---------------------------------------------------------------------------

#define N_IN_MAX  100000
#define N_OT_MAX  50000

__device__ float g_rhs[N_IN_MAX * 64];
__device__ float g_lhs[N_OT_MAX * 64];
__device__ float g_acc[N_IN_MAX * 64];
__device__ float g_cnt[N_IN_MAX];
__device__ float g_Wcomb[64 * 64];
__device__ float g_bfw[64];

// ---------------- zero scratch ----------------
__global__ void zero_kernel(float* __restrict__ acc, float* __restrict__ cnt,
                            int n_acc, int n_cnt) {
    int stride = gridDim.x * blockDim.x;
    int i = blockIdx.x * blockDim.x + threadIdx.x;
    for (int j = i; j < n_acc; j += stride) acc[j] = 0.0f;
    for (int j = i; j < n_cnt; j += stride) cnt[j] = 0.0f;
}

// ---------------- precompute Wcomb = Wf @ Wout[0:64,:], bfw = bf @ Wout[0:64,:] ----
__global__ void precompute_kernel(const float* __restrict__ Wf,
                                  const float* __restrict__ bf,
                                  const float* __restrict__ Wout,
                                  float* __restrict__ Wcomb,
                                  float* __restrict__ bfw) {
    int t = blockIdx.x * blockDim.x + threadIdx.x;
    if (t < 64 * 64) {
        int k = t >> 6, d = t & 63;
        float s = 0.0f;
#pragma unroll 8
        for (int j = 0; j < 64; j++) s += Wf[k * 64 + j] * Wout[j * 64 + d];
        Wcomb[t] = s;
    }
    if (t < 64) {
        float s = 0.0f;
#pragma unroll 8
        for (int j = 0; j < 64; j++) s += bf[j] * Wout[j * 64 + t];
        bfw[t] = s;
    }
}

// ---------------- GEMM: C[M,64] = A[M,64] @ W[64,64] (+bias) ------------------
// 64x64 tile per block, 256 threads, 4x4 register tile per thread.
template <bool HAS_BIAS>
__global__ void gemm64_kernel(const float* __restrict__ A,
                              const float* __restrict__ W,
                              const float* __restrict__ bias,
                              float* __restrict__ C, int M) {
    __shared__ float As[64][65];  // As[k][row]
    __shared__ float Ws[64][65];  // Ws[k][col]
    const int block_row = blockIdx.x * 64;
    const int tid = threadIdx.x;

    for (int i = tid; i < 64 * 64; i += 256) {
        int r = i >> 6, c = i & 63;
        int grow = block_row + r;
        As[c][r] = (grow < M) ? A[(size_t)grow * 64 + c] : 0.0f;
        Ws[r][c] = W[i];
    }
    __syncthreads();

    const int tx = tid & 15;   // col group (4 cols)
    const int ty = tid >> 4;   // row group (4 rows)
    float acc[4][4] = {};
#pragma unroll 8
    for (int k = 0; k < 64; k++) {
        float a0 = As[k][ty * 4 + 0], a1 = As[k][ty * 4 + 1];
        float a2 = As[k][ty * 4 + 2], a3 = As[k][ty * 4 + 3];
        float b0 = Ws[k][tx * 4 + 0], b1 = Ws[k][tx * 4 + 1];
        float b2 = Ws[k][tx * 4 + 2], b3 = Ws[k][tx * 4 + 3];
        acc[0][0] = fmaf(a0, b0, acc[0][0]); acc[0][1] = fmaf(a0, b1, acc[0][1]);
        acc[0][2] = fmaf(a0, b2, acc[0][2]); acc[0][3] = fmaf(a0, b3, acc[0][3]);
        acc[1][0] = fmaf(a1, b0, acc[1][0]); acc[1][1] = fmaf(a1, b1, acc[1][1]);
        acc[1][2] = fmaf(a1, b2, acc[1][2]); acc[1][3] = fmaf(a1, b3, acc[1][3]);
        acc[2][0] = fmaf(a2, b0, acc[2][0]); acc[2][1] = fmaf(a2, b1, acc[2][1]);
        acc[2][2] = fmaf(a2, b2, acc[2][2]); acc[2][3] = fmaf(a2, b3, acc[2][3]);
        acc[3][0] = fmaf(a3, b0, acc[3][0]); acc[3][1] = fmaf(a3, b1, acc[3][1]);
        acc[3][2] = fmaf(a3, b2, acc[3][2]); acc[3][3] = fmaf(a3, b3, acc[3][3]);
    }

    float bv[4] = {0.f, 0.f, 0.f, 0.f};
    if (HAS_BIAS) {
#pragma unroll
        for (int j = 0; j < 4; j++) bv[j] = bias[tx * 4 + j];
    }
#pragma unroll
    for (int i = 0; i < 4; i++) {
        int row = block_row + ty * 4 + i;
        if (row < M) {
            float4 v = make_float4(acc[i][0] + bv[0], acc[i][1] + bv[1],
                                   acc[i][2] + bv[2], acc[i][3] + bv[3]);
            *reinterpret_cast<float4*>(&C[(size_t)row * 64 + tx * 4]) = v;
        }
    }
}

// ---------------- edge kernel: gather + lrelu + red.v4 scatter ----------------
// 16 lanes per edge, one float4 per lane.
__global__ void edge_kernel(const float* __restrict__ rhs,
                            const float* __restrict__ lhs,
                            const int* __restrict__ rj,
                            const int* __restrict__ lj,
                            const float* __restrict__ w,
                            const float* __restrict__ We,
                            float* __restrict__ acc,
                            float* __restrict__ cnt, int E) {
    int gtid = blockIdx.x * blockDim.x + threadIdx.x;
    int e = gtid >> 4;
    if (e >= E) return;
    int lane16 = gtid & 15;

    int r = __ldg(rj + e);
    int l = __ldg(lj + e);
    float wv = __ldg(w + e);

    const float4* rhs4 = reinterpret_cast<const float4*>(rhs);
    const float4* lhs4 = reinterpret_cast<const float4*>(lhs);
    const float4* We4  = reinterpret_cast<const float4*>(We);

    float4 a  = __ldg(rhs4 + (size_t)r * 16 + lane16);
    float4 b  = __ldg(lhs4 + (size_t)l * 16 + lane16);
    float4 we = __ldg(We4 + lane16);

    float4 m;
    m.x = fmaf(wv, we.x, a.x + b.x);
    m.y = fmaf(wv, we.y, a.y + b.y);
    m.z = fmaf(wv, we.z, a.z + b.z);
    m.w = fmaf(wv, we.w, a.w + b.w);
    // leaky_relu(x, 0.01) == max(x,0) + 0.01*min(x,0)
    m.x = fmaxf(m.x, 0.f) + 0.01f * fminf(m.x, 0.f);
    m.y = fmaxf(m.y, 0.f) + 0.01f * fminf(m.y, 0.f);
    m.z = fmaxf(m.z, 0.f) + 0.01f * fminf(m.z, 0.f);
    m.w = fmaxf(m.w, 0.f) + 0.01f * fminf(m.w, 0.f);

    float* dst = acc + (size_t)r * 64 + lane16 * 4;
    asm volatile("red.global.add.v4.f32 [%0], {%1, %2, %3, %4};"
                 :: "l"(dst), "f"(m.x), "f"(m.y), "f"(m.z), "f"(m.w)
                 : "memory");
    if (lane16 == 0) atomicAdd(cnt + r, 1.0f);
}

// ---------------- fused epilogue: K=128 GEMM + rank-1 cnt term + biases --------
// out[i,:] = acc[i]@Wcomb + input[i]@WoutB + cnt[i]*bfw + bout
__global__ void final_kernel(const float* __restrict__ accm,
                             const float* __restrict__ input,
                             const float* __restrict__ cnt,
                             const float* __restrict__ Wcomb,
                             const float* __restrict__ WoutB,
                             const float* __restrict__ bfw,
                             const float* __restrict__ bout,
                             float* __restrict__ out, int M) {
    __shared__ float As[64][65];
    __shared__ float Ws[64][65];
    const int block_row = blockIdx.x * 64;
    const int tid = threadIdx.x;
    const int tx = tid & 15;
    const int ty = tid >> 4;

    float acc[4][4] = {};

#pragma unroll
    for (int p = 0; p < 2; p++) {
        const float* Ap = (p == 0) ? accm : input;
        const float* Wp = (p == 0) ? Wcomb : WoutB;
        for (int i = tid; i < 64 * 64; i += 256) {
            int r = i >> 6, c = i & 63;
            int grow = block_row + r;
            As[c][r] = (grow < M) ? Ap[(size_t)grow * 64 + c] : 0.0f;
            Ws[r][c] = Wp[i];
        }
        __syncthreads();
#pragma unroll 8
        for (int k = 0; k < 64; k++) {
            float a0 = As[k][ty * 4 + 0], a1 = As[k][ty * 4 + 1];
            float a2 = As[k][ty * 4 + 2], a3 = As[k][ty * 4 + 3];
            float b0 = Ws[k][tx * 4 + 0], b1 = Ws[k][tx * 4 + 1];
            float b2 = Ws[k][tx * 4 + 2], b3 = Ws[k][tx * 4 + 3];
            acc[0][0] = fmaf(a0, b0, acc[0][0]); acc[0][1] = fmaf(a0, b1, acc[0][1]);
            acc[0][2] = fmaf(a0, b2, acc[0][2]); acc[0][3] = fmaf(a0, b3, acc[0][3]);
            acc[1][0] = fmaf(a1, b0, acc[1][0]); acc[1][1] = fmaf(a1, b1, acc[1][1]);
            acc[1][2] = fmaf(a1, b2, acc[1][2]); acc[1][3] = fmaf(a1, b3, acc[1][3]);
            acc[2][0] = fmaf(a2, b0, acc[2][0]); acc[2][1] = fmaf(a2, b1, acc[2][1]);
            acc[2][2] = fmaf(a2, b2, acc[2][2]); acc[2][3] = fmaf(a2, b3, acc[2][3]);
            acc[3][0] = fmaf(a3, b0, acc[3][0]); acc[3][1] = fmaf(a3, b1, acc[3][1]);
            acc[3][2] = fmaf(a3, b2, acc[3][2]); acc[3][3] = fmaf(a3, b3, acc[3][3]);
        }
        __syncthreads();
    }

    float bfv[4], bov[4];
#pragma unroll
    for (int j = 0; j < 4; j++) {
        bfv[j] = bfw[tx * 4 + j];
        bov[j] = bout[tx * 4 + j];
    }
#pragma unroll
    for (int i = 0; i < 4; i++) {
        int row = block_row + ty * 4 + i;
        if (row < M) {
            float c = cnt[row];
            float4 v = make_float4(acc[i][0] + c * bfv[0] + bov[0],
                                   acc[i][1] + c * bfv[1] + bov[1],
                                   acc[i][2] + c * bfv[2] + bov[2],
                                   acc[i][3] + c * bfv[3] + bov[3]);
            *reinterpret_cast<float4*>(&out[(size_t)row * 64 + tx * 4]) = v;
        }
    }
}

// ---------------------------------------------------------------------------
extern "C" void kernel_launch(void* const* d_in, const int* in_sizes, int n_in,
                              void* d_out, int out_size) {
    const float* input   = (const float*)d_in[0];   // [N_IN,64]
    const float* other   = (const float*)d_in[1];   // [N_OT,64]
    const int*   rj      = (const int*)d_in[2];     // [E]
    const int*   lj      = (const int*)d_in[3];     // [E]
    const float* weights = (const float*)d_in[4];   // [E,1]
    const float* Wi      = (const float*)d_in[5];   // [64,64]
    const float* bi      = (const float*)d_in[6];   // [64]
    const float* Wo      = (const float*)d_in[7];   // [64,64]
    const float* We      = (const float*)d_in[8];   // [1,64]
    const float* Wf      = (const float*)d_in[9];   // [64,64]
    const float* bf      = (const float*)d_in[10];  // [64]
    const float* Wout    = (const float*)d_in[11];  // [128,64]
    const float* bout    = (const float*)d_in[12];  // [64]
    float* out = (float*)d_out;

    const int N_IN = in_sizes[0] / 64;
    const int N_OT = in_sizes[1] / 64;
    const int E    = in_sizes[2];

    float *rhs, *lhs, *acc, *cnt, *Wcomb, *bfw;
    cudaGetSymbolAddress((void**)&rhs,   g_rhs);
    cudaGetSymbolAddress((void**)&lhs,   g_lhs);
    cudaGetSymbolAddress((void**)&acc,   g_acc);
    cudaGetSymbolAddress((void**)&cnt,   g_cnt);
    cudaGetSymbolAddress((void**)&Wcomb, g_Wcomb);
    cudaGetSymbolAddress((void**)&bfw,   g_bfw);

    // 1. zero accumulators
    zero_kernel<<<2048, 256>>>(acc, cnt, N_IN * 64, N_IN);

    // 2. input-side GEMMs
    gemm64_kernel<true><<<(N_IN + 63) / 64, 256>>>(input, Wi, bi, rhs, N_IN);
    gemm64_kernel<false><<<(N_OT + 63) / 64, 256>>>(other, Wo, nullptr, lhs, N_OT);

    // 3. precompute folded epilogue weights
    precompute_kernel<<<16, 256>>>(Wf, bf, Wout, Wcomb, bfw);

    // 4. edge gather + lrelu + vector-atomic scatter
    {
        long long total = (long long)E * 16;
        int blocks = (int)((total + 255) / 256);
        edge_kernel<<<blocks, 256>>>(rhs, lhs, rj, lj, weights, We, acc, cnt, E);
    }

    // 5. fused epilogue GEMM (K=128) + cnt*bfw + bout
    final_kernel<<<(N_IN + 63) / 64, 256>>>(acc, input, cnt, Wcomb,
                                            Wout + 64 * 64, bfw, bout, out, N_IN);
}